// round 1
// baseline (speedup 1.0000x reference)
#include <cuda_runtime.h>

// MinimalRNN scan: h_t = exp(log_coeffs[t-1]) * h_{t-1} + exp(log_values[t])
// h_0 = exp(log_values[0]); output is h_1..h_T  (shape B x T x H)
//
// Layout: (B, T, H) row-major, H contiguous. One thread per (b, h) channel;
// lanes of a warp cover 32 consecutive h -> every load/store is a coalesced
// 128B transaction. Double-buffered prefetch of U steps keeps ~32 independent
// LDGs in flight per thread to cover DRAM latency with only 512 warps.

#define BB 16
#define TT 4096
#define HH 1024
#define UU 16

__global__ void __launch_bounds__(32)
minrnn_scan_kernel(const float* __restrict__ lc,   // (B, T, H)
                   const float* __restrict__ lv,   // (B, T+1, H)
                   float* __restrict__ out)        // (B, T, H)
{
    const int ch = blockIdx.x * blockDim.x + threadIdx.x;   // 0 .. B*H-1
    const int b  = ch / HH;
    const int h  = ch - b * HH;

    // 32-bit element offsets are safe: max index 16*4097*1024 < 2^31.
    const float* lcp = lc + b * (TT * HH) + h;          // step stride HH
    const float* lvp = lv + b * ((TT + 1) * HH) + h;    // step stride HH
    float*       op  = out + b * (TT * HH) + h;

    float hval = __expf(lvp[0]);
    lvp += HH;   // now lvp[t*HH] = log_values[b, t+1, h]

    float cc[UU], vv[UU];
#pragma unroll
    for (int i = 0; i < UU; i++) {
        cc[i] = lcp[i * HH];
        vv[i] = lvp[i * HH];
    }

    // Main loop: prefetch next group while computing current one.
    for (int t0 = 0; t0 < TT - UU; t0 += UU) {
        float cn[UU], vn[UU];
#pragma unroll
        for (int i = 0; i < UU; i++) {
            cn[i] = lcp[(t0 + UU + i) * HH];
            vn[i] = lvp[(t0 + UU + i) * HH];
        }
#pragma unroll
        for (int i = 0; i < UU; i++) {
            hval = __expf(cc[i]) * hval + __expf(vv[i]);
            op[(t0 + i) * HH] = hval;
        }
#pragma unroll
        for (int i = 0; i < UU; i++) {
            cc[i] = cn[i];
            vv[i] = vn[i];
        }
    }

    // Tail group (no prefetch).
    {
        const int t0 = TT - UU;
#pragma unroll
        for (int i = 0; i < UU; i++) {
            hval = __expf(cc[i]) * hval + __expf(vv[i]);
            op[(t0 + i) * HH] = hval;
        }
    }
}

extern "C" void kernel_launch(void* const* d_in, const int* in_sizes, int n_in,
                              void* d_out, int out_size)
{
    const float* log_coeffs = (const float*)d_in[0];   // (B, T, H)
    const float* log_values = (const float*)d_in[1];   // (B, T+1, H)
    float*       out        = (float*)d_out;           // (B, T, H)

    const int channels = BB * HH;        // 16384
    const int threads  = 32;             // 1 warp per block -> even SM spread
    const int blocks   = channels / threads;   // 512

    minrnn_scan_kernel<<<blocks, threads>>>(log_coeffs, log_values, out);
}

// round 2
// speedup vs baseline: 1.0656x; 1.0656x over previous
#include <cuda_runtime.h>

// MinimalRNN scan: h_t = exp(log_coeffs[t-1]) * h_{t-1} + exp(log_values[t])
// h_0 = exp(log_values[0]); output h_1..h_T  (B, T, H) row-major.
//
// One thread per (b,h) channel; 32 lanes = 32 consecutive h -> every access
// is a full 128B coalesced line. 128-thread blocks put one warp on each of
// the 4 SMSPs (MUFU/issue throughput). Ping-pong prefetch of U=32 steps
// keeps 64 independent LDGs in flight per thread (~4MB chip-wide) to cover
// DRAM latency with only 512 total warps.

#define BB 16
#define TT 4096
#define HH 1024
#define UU 32

__global__ void __launch_bounds__(128)
minrnn_scan_kernel(const float* __restrict__ lc,   // (B, T, H)
                   const float* __restrict__ lv,   // (B, T+1, H)
                   float* __restrict__ out)        // (B, T, H)
{
    const int ch = blockIdx.x * blockDim.x + threadIdx.x;   // 0 .. B*H-1
    const int b  = ch >> 10;          // / HH
    const int h  = ch & (HH - 1);     // % HH

    // 32-bit element offsets are safe: max index 16*4097*1024 < 2^31.
    const float* lcp = lc + b * (TT * HH) + h;          // step stride HH
    const float* lvp = lv + b * ((TT + 1) * HH) + h;    // step stride HH
    float*       op  = out + b * (TT * HH) + h;

    float hval = __expf(lvp[0]);
    lvp += HH;   // lvp[t*HH] = log_values[b, t+1, h]

    float ca[UU], va[UU], cb[UU], vb[UU];

    // Prefetch group 0 into buffer A.
#pragma unroll
    for (int i = 0; i < UU; i++) {
        ca[i] = lcp[i * HH];
        va[i] = lvp[i * HH];
    }

    // Ping-pong: compute A while B loads, compute B while A loads.
    for (int t0 = 0; t0 < TT; t0 += 2 * UU) {
        // Prefetch group t0+UU into B.
#pragma unroll
        for (int i = 0; i < UU; i++) {
            cb[i] = lcp[(t0 + UU + i) * HH];
            vb[i] = lvp[(t0 + UU + i) * HH];
        }
        // Compute group t0 from A.
#pragma unroll
        for (int i = 0; i < UU; i++) {
            hval = __expf(ca[i]) * hval + __expf(va[i]);
            op[(t0 + i) * HH] = hval;
        }
        // Prefetch group t0+2U into A (skip on last outer iteration).
        if (t0 + 2 * UU < TT) {
#pragma unroll
            for (int i = 0; i < UU; i++) {
                ca[i] = lcp[(t0 + 2 * UU + i) * HH];
                va[i] = lvp[(t0 + 2 * UU + i) * HH];
            }
        }
        // Compute group t0+U from B.
#pragma unroll
        for (int i = 0; i < UU; i++) {
            hval = __expf(cb[i]) * hval + __expf(vb[i]);
            op[(t0 + UU + i) * HH] = hval;
        }
    }
}

extern "C" void kernel_launch(void* const* d_in, const int* in_sizes, int n_in,
                              void* d_out, int out_size)
{
    const float* log_coeffs = (const float*)d_in[0];   // (B, T, H)
    const float* log_values = (const float*)d_in[1];   // (B, T+1, H)
    float*       out        = (float*)d_out;           // (B, T, H)

    const int channels = BB * HH;                 // 16384
    const int threads  = 128;                     // 4 warps -> all 4 SMSPs
    const int blocks   = channels / threads;      // 128

    minrnn_scan_kernel<<<blocks, threads>>>(log_coeffs, log_values, out);
}